// round 11
// baseline (speedup 1.0000x reference)
#include <cuda_runtime.h>
#include <cuda_fp16.h>
#include <math.h>
#include <cfloat>

#define BB 2
#define NN 30
#define CC 320
#define FHW 4096
#define PH 32
#define PW 32
#define MM 31

#define RA_BLOCKS2 (BB*NN*PH*2)        // 3840 half-channel roialign blocks
#define RED_PIX    (2*BB*FHW)          // 16384 (attn + nhs reductions)
#define RED_BLOCKS ((RED_PIX+9)/10)    // 1639 blocks x 5 warps x 2 pixels
#define K2_TOTAL   (BB*(NN+1)*4)       // 248 slot tasks

// Scratch (static device memory)
__device__ __half g_roi_h[BB*NN*PH*PW*CC];  // 39.3 MB, fp16 roi feats
__device__ float g_fsum[BB*FHW];
__device__ float g_fred[BB*FHW];
__device__ float g_fwT[BB*FHW*32];          // [b][pix][slot] masked logits (-FLT_MAX = dead)
__device__ float g_fw0[BB*FHW];             // raw slot-0 fw (pre-mask, for mp0)
__device__ float g_mp4[BB*MM*4];
__device__ float g_scale[BB*MM];
__device__ int   g_ctr;

__device__ __forceinline__ float warpReduceSum(float v){
  #pragma unroll
  for (int o=16;o>0;o>>=1) v += __shfl_xor_sync(0xffffffffu, v, o);
  return v;
}
__device__ __forceinline__ float warpReduceMax(float v){
  #pragma unroll
  for (int o=16;o>0;o>>=1) v = fmaxf(v, __shfl_xor_sync(0xffffffffu, v, o));
  return v;
}

__device__ __forceinline__ float4 unpack_h4(uint2 raw){
  __half2 h0 = *reinterpret_cast<__half2*>(&raw.x);
  __half2 h1 = *reinterpret_cast<__half2*>(&raw.y);
  float2 f0 = __half22float2(h0);
  float2 f1 = __half22float2(h1);
  return make_float4(f0.x, f0.y, f1.x, f1.y);
}
__device__ __forceinline__ uint2 pack_h4(float4 v){
  __half2 h0 = __floats2half2_rn(v.x, v.y);
  __half2 h1 = __floats2half2_rn(v.z, v.w);
  uint2 u;
  u.x = *reinterpret_cast<unsigned*>(&h0);
  u.y = *reinterpret_cast<unsigned*>(&h1);
  return u;
}

// ---------------------------------------------------------------------------
// Kernel A: channel reductions, 2 pixels per warp (MLP x2).
// Also resets the slot-task counter for this iteration.
// ---------------------------------------------------------------------------
__global__ void __launch_bounds__(160) k_red(
    const float* __restrict__ nhs,
    const float* __restrict__ attn,
    const float* __restrict__ w_reduce)
{
  int bid = blockIdx.x;
  int t = threadIdx.x;
  if (bid == 0 && t == 0) g_ctr = 0;

  int wid = t >> 5, lane = t & 31;
  int p0 = (bid*5 + wid)*2;
  const float4* w4 = (const float4*)w_reduce;
  float wv[3]; float4 wr[3];
  #pragma unroll
  for (int k=0;k<3;k++){
    int i = lane + k*32;
    wr[k] = (i < 80) ? w4[i] : make_float4(0.f,0.f,0.f,0.f);
    (void)wv;
  }

  float sA=0.f, srA=0.f, sB=0.f, srB=0.f;
  // batch all loads for both pixels up-front (independent)
  #pragma unroll
  for (int px=0; px<2; px++){
    int p = p0 + px;
    if (p >= RED_PIX) break;
    int isN = p >> 13;
    int b   = (p >> 12) & 1;
    int pix = p & 4095;
    const float4* s4 = (const float4*)((isN ? nhs : attn) + (size_t)(b*FHW + pix)*CC);
    float s = 0.f, sr = 0.f;
    #pragma unroll
    for (int k=0;k<3;k++){
      int i = lane + k*32;
      if (i < 80){
        float4 a = s4[i];
        s  += a.x + a.y + a.z + a.w;
        sr += a.x*wr[k].x + a.y*wr[k].y + a.z*wr[k].z + a.w*wr[k].w;
      }
    }
    if (px == 0){ sA = s; srA = sr; } else { sB = s; srB = sr; }
  }

  #pragma unroll
  for (int px=0; px<2; px++){
    int p = p0 + px;
    if (p >= RED_PIX) break;
    float s  = warpReduceSum(px ? sB : sA);
    float sr = warpReduceSum(px ? srB : srA);
    if (lane == 0){
      int isN = p >> 13;
      int b   = (p >> 12) & 1;
      int pix = p & 4095;
      if (isN){ g_fsum[b*FHW+pix] = s; g_fred[b*FHW+pix] = sr; }
      else {
        g_fwT[((size_t)b*FHW + pix)*32] = (s != 0.f) ? sr : -FLT_MAX;
        g_fw0[b*FHW + pix] = sr;
      }
    }
  }
}

// ---------------------------------------------------------------------------
// Kernel B (fused, no internal dependency):
//  - blocks [0, K2_TOTAL): slot tasks (depend only on kernel A)
//  - blocks [K2_TOTAL, ...): separable ROI-align (depends only on nhs)
// Slot blocks lead the grid so they dispatch in wave 1 and overlap RA.
// vrow held in fp16 (uint2 = half4): half the LDS/STS bytes, half the smem.
// ---------------------------------------------------------------------------
__global__ void __launch_bounds__(160) k_main(
    const float* __restrict__ nhs,
    const float* __restrict__ boxes,
    const int* __restrict__ masks,
    const int* __restrict__ perm,
    const float* __restrict__ w1, const float* __restrict__ b1,
    const float* __restrict__ w2, const float* __restrict__ b2)
{
  __shared__ uint2 vrowh[32*40];     // 10.2 KB; slot path reuses as rs/rr maps
  __shared__ float s_B[PW][3];
  __shared__ int   s_i[PW][3];

  int bid = blockIdx.x;
  int t = threadIdx.x;

  if (bid < K2_TOTAL){
    // ================= slot-task path =================
    float* rs_s = (float*)vrowh;          // 1024 floats
    float* rr_s = rs_s + PH*PW;           // 1024 floats
    __shared__ float smax[5];

    int b = bid / ((NN+1)*4);
    int rem = bid % ((NN+1)*4);
    int s = rem >> 2;
    int chunk = rem & 3;
    float lmax = -FLT_MAX;

    if (s < NN){
      int n = s;
      int m = 1 + n;
      float* fwT = g_fwT + (size_t)b*FHW*32 + m;
      if (masks[b*NN+n] == 0){
        for (int i = chunk*1024 + t; i < (chunk+1)*1024; i += 160)
          fwT[(size_t)i*32] = -FLT_MAX;
        lmax = 0.f;
      } else {
        const float* bx = boxes + (b*NN+n)*4;
        float x1 = bx[0]*64.f - 0.5f, y1 = bx[1]*64.f - 0.5f;
        float bw = (bx[2]*64.f - 0.5f - x1)*(1.f/PW);
        float bh = (bx[3]*64.f - 0.5f - y1)*(1.f/PH);

        const float* fs = g_fsum + b*FHW;
        const float* fr = g_fred + b*FHW;
        for (int cell = t; cell < PH*PW; cell += 160){
          int ph = cell >> 5, pw = cell & 31;
          float as = 0.f, ar = 0.f;
          #pragma unroll
          for (int sy=0; sy<2; sy++){
            float y = y1 + ((float)(2*ph+sy)+0.5f)*0.5f*bh;
            #pragma unroll
            for (int sx=0; sx<2; sx++){
              float x = x1 + ((float)(2*pw+sx)+0.5f)*0.5f*bw;
              bool valid = (y > -1.f) && (y < 64.f) && (x > -1.f) && (x < 64.f);
              float yc = fminf(fmaxf(y,0.f),63.f);
              float xc = fminf(fmaxf(x,0.f),63.f);
              int y0 = (int)floorf(yc), x0 = (int)floorf(xc);
              int y1i = min(y0+1,63), x1i = min(x0+1,63);
              float wy = yc - (float)y0, wx = xc - (float)x0;
              float c00 = (1.f-wy)*(1.f-wx), c01 = (1.f-wy)*wx;
              float c10 = wy*(1.f-wx),       c11 = wy*wx;
              float vs = fs[y0*64+x0]*c00 + fs[y0*64+x1i]*c01
                       + fs[y1i*64+x0]*c10 + fs[y1i*64+x1i]*c11;
              float vr = fr[y0*64+x0]*c00 + fr[y0*64+x1i]*c01
                       + fr[y1i*64+x0]*c10 + fr[y1i*64+x1i]*c11;
              if (valid){ as += vs; ar += vr; }
            }
          }
          rs_s[cell] = as * 0.25f;
          rr_s[cell] = ar * 0.25f;
        }
        __syncthreads();

        float inv_bw = 1.f/bw, inv_bh = 1.f/bh;
        for (int i = chunk*1024 + t; i < (chunk+1)*1024; i += 160){
          int h = i >> 6, w = i & 63;
          float ry = ((float)h - y1)*inv_bh - 0.5f;
          float rx = ((float)w - x1)*inv_bw - 0.5f;
          bool valid = (ry > -1.f) && (ry < 32.f) && (rx > -1.f) && (rx < 32.f);
          float yc = fminf(fmaxf(ry,0.f),31.f);
          float xc = fminf(fmaxf(rx,0.f),31.f);
          int y0 = (int)floorf(yc), x0 = (int)floorf(xc);
          int y1i = min(y0+1,31), x1i = min(x0+1,31);
          float wy = yc - (float)y0, wx = xc - (float)x0;
          float c00 = (1.f-wy)*(1.f-wx), c01 = (1.f-wy)*wx;
          float c10 = wy*(1.f-wx),       c11 = wy*wx;
          float vs = rs_s[y0*32+x0]*c00 + rs_s[y0*32+x1i]*c01
                   + rs_s[y1i*32+x0]*c10 + rs_s[y1i*32+x1i]*c11;
          float vr = rr_s[y0*32+x0]*c00 + rr_s[y0*32+x1i]*c01
                   + rr_s[y1i*32+x0]*c10 + rr_s[y1i*32+x1i]*c11;
          if (!valid){ vs = 0.f; vr = 0.f; }
          lmax = fmaxf(lmax, vr);
          fwT[(size_t)i*32] = (vs != 0.f) ? vr : -FLT_MAX;
        }
      }
    } else {
      const float* fwp = g_fw0 + b*FHW;
      for (int i = chunk*1024 + t; i < (chunk+1)*1024; i += 160)
        lmax = fmaxf(lmax, fwp[i]);
    }

    lmax = warpReduceMax(lmax);
    if ((t & 31) == 0) smax[t>>5] = lmax;
    __syncthreads();
    if (t < 32){
      float v = (t < 5) ? smax[t] : -FLT_MAX;
      v = warpReduceMax(v);
      if (t == 0){
        int m = (s < NN) ? (1 + s) : 0;
        g_mp4[(b*MM + m)*4 + chunk] = v;
      }
    }

    // -------- last-arrival epilogue (counter scoped to slot blocks) --------
    __threadfence();
    __syncthreads();
    __shared__ int s_old2;
    if (t == 0) s_old2 = atomicAdd(&g_ctr, 1);
    __syncthreads();
    if (s_old2 != K2_TOTAL - 1) return;
    __threadfence();

    __shared__ float mp_s[BB][MM], mg[BB][MM], hh[BB][MM];
    if (t < BB*MM){
      int bb = t/MM, m = t%MM;
      const float* p = g_mp4 + (bb*MM + m)*4;
      mp_s[bb][m] = fmaxf(fmaxf(p[0],p[1]), fmaxf(p[2],p[3]));
    }
    __syncthreads();
    if (t < BB*MM){
      int bb = t/MM, i = t%MM;
      mg[bb][i] = (i == 0) ? mp_s[bb][0] : mp_s[bb][1 + perm[i-1]];
    }
    __syncthreads();
    if (t < BB*MM){
      int bb = t/MM, i = t%MM;
      float a = b1[i];
      #pragma unroll
      for (int j=0;j<MM;j++) a += mg[bb][j]*w1[j*MM+i];
      hh[bb][i] = fmaxf(a, 0.f);
    }
    __syncthreads();
    if (t < BB*MM){
      int bb = t/MM, i = t%MM;
      float a = b2[i];
      #pragma unroll
      for (int j=0;j<MM;j++) a += hh[bb][j]*w2[j*MM+i];
      float sg = 1.f/(1.f + expf(-a));
      if (i == 0) g_scale[bb*MM] = sg; else g_scale[bb*MM + 1 + perm[i-1]] = sg;
    }
    return;
  }

  // ================= roialign path =================
  int r = bid - K2_TOTAL;
  int chalf = r & 1;
  r >>= 1;
  int b  = r / (NN*PH);
  int rem = r % (NN*PH);
  int n  = rem / PH;
  int ph = rem % PH;
  if (masks[b*NN+n] == 0) return;

  int tq = t % 40;
  int cg = t / 40;

  const float* bx = boxes + (b*NN+n)*4;
  float x1 = bx[0]*64.f - 0.5f;
  float y1 = bx[1]*64.f - 0.5f;
  float bw = (bx[2]*64.f - 0.5f - x1) * (1.f/PW);
  float bh = (bx[3]*64.f - 0.5f - y1) * (1.f/PH);

  // --- row (y) coefficients ---
  float Ac0=0.f, Ac1=0.f, Ac2=0.f;
  float yA = y1 + ((float)(2*ph)+0.5f)*0.5f*bh;
  float yB = yA + 0.5f*bh;
  float ycA = fminf(fmaxf(yA,0.f),63.f);
  float ycB = fminf(fmaxf(yB,0.f),63.f);
  int y0A = (int)floorf(ycA), y0B = (int)floorf(ycB);
  int r0 = y0A;
  {
    if (yA > -1.f && yA < 64.f){
      int y1A = min(y0A+1,63);
      float wy = ycA - (float)y0A;
      float w0 = 0.5f*(1.f-wy), w1v = 0.5f*wy;
      int o1 = y1A - r0;
      Ac0 += w0;
      if (o1==0) Ac0 += w1v; else if (o1==1) Ac1 += w1v; else Ac2 += w1v;
    }
    if (yB > -1.f && yB < 64.f){
      int y1B = min(y0B+1,63);
      float wy = ycB - (float)y0B;
      float w0 = 0.5f*(1.f-wy), w1v = 0.5f*wy;
      int o0 = y0B - r0, o1 = y1B - r0;
      if (o0==0) Ac0 += w0; else if (o0==1) Ac1 += w0; else Ac2 += w0;
      if (o1==0) Ac0 += w1v; else if (o1==1) Ac1 += w1v; else Ac2 += w1v;
    }
  }
  bool anyA = (Ac0 != 0.f) || (Ac1 != 0.f) || (Ac2 != 0.f);

  // --- x patch bounds ---
  float xFirst = x1 + 0.25f*bw;
  float xLast  = x1 + 63.5f*0.5f*bw;
  int c_lo = (int)floorf(fminf(fmaxf(xFirst,0.f),63.f));
  int c_hi = min((int)floorf(fminf(fmaxf(xLast ,0.f),63.f)) + 1, 63);
  c_hi = min(c_hi, c_lo + 31);
  int W = c_hi - c_lo + 1;

  // --- stage 1: vertical resample (fp32 math, fp16 vrow store) ---
  if (anyA){
    int rr0 = min(r0  ,63);
    int rr1 = min(r0+1,63);
    int rr2 = min(r0+2,63);
    const float4* base4 = (const float4*)(nhs + (size_t)b*FHW*CC) + chalf*40 + tq;
    const float4* p0 = base4 + (size_t)rr0*64*80;
    const float4* p1 = base4 + (size_t)rr1*64*80;
    const float4* p2 = base4 + (size_t)rr2*64*80;
    #pragma unroll 4
    for (int col=c_lo+cg; col<=c_hi; col+=4){
      float4 a = p0[col*80];
      float4 bb2 = p1[col*80];
      float4 cc2 = p2[col*80];
      float4 v;
      v.x = Ac0*a.x + Ac1*bb2.x + Ac2*cc2.x;
      v.y = Ac0*a.y + Ac1*bb2.y + Ac2*cc2.y;
      v.z = Ac0*a.z + Ac1*bb2.z + Ac2*cc2.z;
      v.w = Ac0*a.w + Ac1*bb2.w + Ac2*cc2.w;
      vrowh[(col-c_lo)*40 + tq] = pack_h4(v);
    }
  } else {
    uint2 z = make_uint2(0u,0u);
    for (int col=cg; col<W; col+=4) vrowh[col*40 + tq] = z;
  }

  // --- per-cell x coefficients + tap offsets ---
  if (t < PW){
    int pw = t;
    float Bc0=0.f, Bc1=0.f, Bc2=0.f;
    float xA = x1 + ((float)(2*pw)+0.5f)*0.5f*bw;
    float xB = xA + 0.5f*bw;
    float xcA = fminf(fmaxf(xA,0.f),63.f);
    float xcB = fminf(fmaxf(xB,0.f),63.f);
    int x0A = (int)floorf(xcA), x0B = (int)floorf(xcB);
    int cb = x0A;
    if (xA > -1.f && xA < 64.f){
      int x1A = min(x0A+1,63);
      float wx = xcA - (float)x0A;
      float w0 = 0.5f*(1.f-wx), w1v = 0.5f*wx;
      int o1 = x1A - cb;
      Bc0 += w0;
      if (o1==0) Bc0 += w1v; else if (o1==1) Bc1 += w1v; else Bc2 += w1v;
    }
    if (xB > -1.f && xB < 64.f){
      int x1B = min(x0B+1,63);
      float wx = xcB - (float)x0B;
      float w0 = 0.5f*(1.f-wx), w1v = 0.5f*wx;
      int o0 = x0B - cb, o1 = x1B - cb;
      if (o0==0) Bc0 += w0; else if (o0==1) Bc1 += w0; else Bc2 += w0;
      if (o1==0) Bc0 += w1v; else if (o1==1) Bc1 += w1v; else Bc2 += w1v;
    }
    int cbr = cb - c_lo;
    s_B[pw][0] = Bc0; s_B[pw][1] = Bc1; s_B[pw][2] = Bc2;
    s_i[pw][0] = min(cbr  , W-1)*40;
    s_i[pw][1] = min(cbr+1, W-1)*40;
    s_i[pw][2] = min(cbr+2, W-1)*40;
  }
  __syncthreads();

  // --- stage 2: 8 consecutive cells per thread, sliding 3-tap window ---
  {
    int base = cg*8;
    uint2* rdst2 = (uint2*)(g_roi_h + (((size_t)(b*NN+n)*PH + ph)*PW)*CC) + chalf*40 + tq;
    int cur0 = s_i[base][0], cur1 = s_i[base][1], cur2 = s_i[base][2];
    float4 v0 = unpack_h4(vrowh[cur0+tq]);
    float4 v1 = unpack_h4(vrowh[cur1+tq]);
    float4 v2 = unpack_h4(vrowh[cur2+tq]);
    #pragma unroll
    for (int k=0;k<8;k++){
      int cell = base + k;
      if (k > 0){
        int n0 = s_i[cell][0];
        if (n0 != cur0){
          if (n0 == cur1){
            v0 = v1; v1 = v2;
            cur0 = cur1; cur1 = cur2;
            cur2 = s_i[cell][2];
            v2 = unpack_h4(vrowh[cur2+tq]);
          } else {
            cur0 = n0; cur1 = s_i[cell][1]; cur2 = s_i[cell][2];
            v0 = unpack_h4(vrowh[cur0+tq]);
            v1 = unpack_h4(vrowh[cur1+tq]);
            v2 = unpack_h4(vrowh[cur2+tq]);
          }
        }
      }
      float B0 = s_B[cell][0], B1 = s_B[cell][1], B2 = s_B[cell][2];
      float4 v;
      v.x = B0*v0.x + B1*v1.x + B2*v2.x;
      v.y = B0*v0.y + B1*v1.y + B2*v2.y;
      v.z = B0*v0.z + B1*v1.z + B2*v2.z;
      v.w = B0*v0.w + B1*v1.w + B2*v2.w;
      rdst2[cell*80] = pack_h4(v);
    }
  }
}

// ---------------------------------------------------------------------------
// Kernel C: 4 pixels per block; coalesced logit prologue on warps 0-3,
// fp16 tap accumulation on all 320 threads.
// ---------------------------------------------------------------------------
__global__ void __launch_bounds__(320) k_final(
    const float* __restrict__ attn,
    const float* __restrict__ boxes,
    float* __restrict__ out)
{
  int pix0 = blockIdx.x*4, b = blockIdx.y;
  int t = threadIdx.x;
  int wid = t >> 5;
  __shared__ float s_w0[4];
  __shared__ float s_coef[4][NN][4];
  __shared__ int   s_base[4][NN][4];
  __shared__ int   s_cnt[4];

  if (wid < 4){
    int pix = pix0 + wid;
    int m = t & 31;
    float fwv = g_fwT[((size_t)b*FHW + pix)*32 + m];
    float sc  = (m < MM) ? g_scale[b*MM + m] : 0.f;
    bool live = (m < MM) && (fwv > -1e37f);
    float logit = live ? fwv*sc : -FLT_MAX;
    float mx = warpReduceMax(logit);
    float e = live ? expf(logit - mx) : 0.f;
    float sum = warpReduceSum(e);
    float w = e / sum;
    if (m == 0) s_w0[wid] = w;

    bool act = (m >= 1) && (m < MM) && (w > 0.f);
    unsigned amask = __ballot_sync(0xffffffffu, act);
    if (act){
      int slot = __popc(amask & ((1u << m) - 1u));
      int n = m - 1;
      const float* bx = boxes + (b*NN+n)*4;
      float x1 = bx[0]*64.f - 0.5f, y1 = bx[1]*64.f - 0.5f;
      float bw = (bx[2]*64.f - 0.5f - x1)*(1.f/PW);
      float bh = (bx[3]*64.f - 0.5f - y1)*(1.f/PH);
      int h = pix >> 6, xw = pix & 63;
      float ry = ((float)h - y1)/bh - 0.5f;
      float rx = ((float)xw - x1)/bw - 0.5f;
      float yc = fminf(fmaxf(ry,0.f),31.f);
      float xc = fminf(fmaxf(rx,0.f),31.f);
      int y0 = (int)floorf(yc), x0 = (int)floorf(xc);
      int y1i = min(y0+1,31), x1i = min(x0+1,31);
      float wy = yc - (float)y0, wx = xc - (float)x0;
      int rb = (b*NN+n)*PH*PW;
      s_coef[wid][slot][0] = w*(1.f-wy)*(1.f-wx); s_base[wid][slot][0] = (rb + y0 *32 + x0 )*(CC/4);
      s_coef[wid][slot][1] = w*(1.f-wy)*wx;       s_base[wid][slot][1] = (rb + y0 *32 + x1i)*(CC/4);
      s_coef[wid][slot][2] = w*wy*(1.f-wx);       s_base[wid][slot][2] = (rb + y1i*32 + x0 )*(CC/4);
      s_coef[wid][slot][3] = w*wy*wx;             s_base[wid][slot][3] = (rb + y1i*32 + x1i)*(CC/4);
    }
    if (m == 0) s_cnt[wid] = __popc(amask);
  }
  __syncthreads();

  int lp = t / 80;          // local pixel 0..3
  int ci = t % 80;          // uint2 (4-channel) index
  int pix = pix0 + lp;
  const float4* a4 = (const float4*)(attn + (size_t)(b*FHW + pix)*CC);
  const uint2* r2 = (const uint2*)g_roi_h;
  float4 av = a4[ci];
  float w0 = s_w0[lp];
  float4 acc = make_float4(w0*av.x, w0*av.y, w0*av.z, w0*av.w);
  int cnt = s_cnt[lp];
  for (int k=0;k<cnt;k++){
    #pragma unroll
    for (int j=0;j<4;j++){
      float cf = s_coef[lp][k][j];
      float4 f = unpack_h4(r2[s_base[lp][k][j] + ci]);
      acc.x += cf*f.x; acc.y += cf*f.y; acc.z += cf*f.z; acc.w += cf*f.w;
    }
  }
  ((float4*)(out + (size_t)(b*FHW + pix)*CC))[ci] = acc;
}

// ---------------------------------------------------------------------------
extern "C" void kernel_launch(void* const* d_in, const int* in_sizes, int n_in,
                              void* d_out, int out_size) {
  const float* nhs      = (const float*)d_in[0];
  const float* attn     = (const float*)d_in[1];
  const float* boxes    = (const float*)d_in[2];
  const int*   masks    = (const int*)  d_in[3];
  const int*   perm     = (const int*)  d_in[4];
  const float* w_reduce = (const float*)d_in[5];
  const float* w1       = (const float*)d_in[6];
  const float* b1       = (const float*)d_in[7];
  const float* w2       = (const float*)d_in[8];
  const float* b2       = (const float*)d_in[9];
  float* out = (float*)d_out;

  k_red<<<RED_BLOCKS, 160>>>(nhs, attn, w_reduce);
  k_main<<<K2_TOTAL + RA_BLOCKS2, 160>>>(nhs, boxes, masks, perm, w1, b1, w2, b2);
  k_final<<<dim3(FHW/4, BB), 320>>>(attn, boxes, out);
}

// round 12
// speedup vs baseline: 1.0113x; 1.0113x over previous
#include <cuda_runtime.h>
#include <cuda_fp16.h>
#include <math.h>
#include <cfloat>

#define BB 2
#define NN 30
#define CC 320
#define FHW 4096
#define PH 32
#define PW 32
#define MM 31

#define RA_BLOCKS2 (BB*NN*PH*2)        // 3840 half-channel roialign blocks
#define RED_PIX    (2*BB*FHW)          // 16384 (attn + nhs reductions)
#define RED_BLOCKS ((RED_PIX+4)/5)     // 3277 blocks x 5 warps x 1 pixel
#define K2_TOTAL   (BB*(NN+1)*4)       // 248 slot tasks

// Scratch (static device memory)
__device__ __half g_roi_h[BB*NN*PH*PW*CC];  // 39.3 MB, fp16 roi feats
__device__ float g_fsum[BB*FHW];
__device__ float g_fred[BB*FHW];
__device__ float g_fwT[BB*FHW*32];          // [b][pix][slot] masked logits (-FLT_MAX = dead)
__device__ float g_fw0[BB*FHW];             // raw slot-0 fw (pre-mask, for mp0)
__device__ float g_mp4[BB*MM*4];
__device__ float g_scale[BB*MM];
__device__ int   g_ctr;

__device__ __forceinline__ float warpReduceSum(float v){
  #pragma unroll
  for (int o=16;o>0;o>>=1) v += __shfl_xor_sync(0xffffffffu, v, o);
  return v;
}
__device__ __forceinline__ float warpReduceMax(float v){
  #pragma unroll
  for (int o=16;o>0;o>>=1) v = fmaxf(v, __shfl_xor_sync(0xffffffffu, v, o));
  return v;
}

__device__ __forceinline__ float4 unpack_h4(uint2 raw){
  __half2 h0 = *reinterpret_cast<__half2*>(&raw.x);
  __half2 h1 = *reinterpret_cast<__half2*>(&raw.y);
  float2 f0 = __half22float2(h0);
  float2 f1 = __half22float2(h1);
  return make_float4(f0.x, f0.y, f1.x, f1.y);
}
__device__ __forceinline__ uint2 pack_h4(float4 v){
  __half2 h0 = __floats2half2_rn(v.x, v.y);
  __half2 h1 = __floats2half2_rn(v.z, v.w);
  uint2 u;
  u.x = *reinterpret_cast<unsigned*>(&h0);
  u.y = *reinterpret_cast<unsigned*>(&h1);
  return u;
}

// ---------------------------------------------------------------------------
// Kernel A: channel reductions, warp per pixel (round-10 proven shape).
// Also resets the slot-task counter for this iteration.
// ---------------------------------------------------------------------------
__global__ void __launch_bounds__(160) k_red(
    const float* __restrict__ nhs,
    const float* __restrict__ attn,
    const float* __restrict__ w_reduce)
{
  int bid = blockIdx.x;
  int t = threadIdx.x;
  if (bid == 0 && t == 0) g_ctr = 0;

  int wid = t >> 5, lane = t & 31;
  int p = bid*5 + wid;
  if (p >= RED_PIX) return;
  int isN = p >> 13;
  int b   = (p >> 12) & 1;
  int pix = p & 4095;
  const float* src = (isN ? nhs : attn) + (size_t)(b*FHW + pix)*CC;
  const float4* s4 = (const float4*)src;
  const float4* w4 = (const float4*)w_reduce;
  float s = 0.f, sr = 0.f;
  #pragma unroll
  for (int k=0;k<3;k++){
    int i = lane + k*32;
    if (i < 80){
      float4 a = s4[i]; float4 w = w4[i];
      s  += a.x + a.y + a.z + a.w;
      sr += a.x*w.x + a.y*w.y + a.z*w.z + a.w*w.w;
    }
  }
  s  = warpReduceSum(s);
  sr = warpReduceSum(sr);
  if (lane == 0){
    if (isN){ g_fsum[b*FHW+pix] = s; g_fred[b*FHW+pix] = sr; }
    else {
      g_fwT[((size_t)b*FHW + pix)*32] = (s != 0.f) ? sr : -FLT_MAX;
      g_fw0[b*FHW + pix] = sr;
    }
  }
}

// ---------------------------------------------------------------------------
// Kernel B (fused, no internal dependency):
//  - blocks [0, K2_TOTAL): slot tasks (depend only on kernel A)
//  - blocks [K2_TOTAL, ...): separable ROI-align (depends only on nhs)
// Slot blocks lead the grid so they dispatch in wave 1 and overlap RA.
// vrow held in fp16 (uint2 = half4): half the LDS/STS bytes, half the smem.
// ---------------------------------------------------------------------------
__global__ void __launch_bounds__(160) k_main(
    const float* __restrict__ nhs,
    const float* __restrict__ boxes,
    const int* __restrict__ masks,
    const int* __restrict__ perm,
    const float* __restrict__ w1, const float* __restrict__ b1,
    const float* __restrict__ w2, const float* __restrict__ b2)
{
  __shared__ uint2 vrowh[32*40];     // 10.2 KB; slot path reuses as rs/rr maps
  __shared__ float s_B[PW][3];
  __shared__ int   s_i[PW][3];

  int bid = blockIdx.x;
  int t = threadIdx.x;

  if (bid < K2_TOTAL){
    // ================= slot-task path =================
    float* rs_s = (float*)vrowh;          // 1024 floats
    float* rr_s = rs_s + PH*PW;           // 1024 floats
    __shared__ float smax[5];

    int b = bid / ((NN+1)*4);
    int rem = bid % ((NN+1)*4);
    int s = rem >> 2;
    int chunk = rem & 3;
    float lmax = -FLT_MAX;

    if (s < NN){
      int n = s;
      int m = 1 + n;
      float* fwT = g_fwT + (size_t)b*FHW*32 + m;
      if (masks[b*NN+n] == 0){
        for (int i = chunk*1024 + t; i < (chunk+1)*1024; i += 160)
          fwT[(size_t)i*32] = -FLT_MAX;
        lmax = 0.f;
      } else {
        const float* bx = boxes + (b*NN+n)*4;
        float x1 = bx[0]*64.f - 0.5f, y1 = bx[1]*64.f - 0.5f;
        float bw = (bx[2]*64.f - 0.5f - x1)*(1.f/PW);
        float bh = (bx[3]*64.f - 0.5f - y1)*(1.f/PH);

        const float* fs = g_fsum + b*FHW;
        const float* fr = g_fred + b*FHW;
        for (int cell = t; cell < PH*PW; cell += 160){
          int ph = cell >> 5, pw = cell & 31;
          float as = 0.f, ar = 0.f;
          #pragma unroll
          for (int sy=0; sy<2; sy++){
            float y = y1 + ((float)(2*ph+sy)+0.5f)*0.5f*bh;
            #pragma unroll
            for (int sx=0; sx<2; sx++){
              float x = x1 + ((float)(2*pw+sx)+0.5f)*0.5f*bw;
              bool valid = (y > -1.f) && (y < 64.f) && (x > -1.f) && (x < 64.f);
              float yc = fminf(fmaxf(y,0.f),63.f);
              float xc = fminf(fmaxf(x,0.f),63.f);
              int y0 = (int)floorf(yc), x0 = (int)floorf(xc);
              int y1i = min(y0+1,63), x1i = min(x0+1,63);
              float wy = yc - (float)y0, wx = xc - (float)x0;
              float c00 = (1.f-wy)*(1.f-wx), c01 = (1.f-wy)*wx;
              float c10 = wy*(1.f-wx),       c11 = wy*wx;
              float vs = fs[y0*64+x0]*c00 + fs[y0*64+x1i]*c01
                       + fs[y1i*64+x0]*c10 + fs[y1i*64+x1i]*c11;
              float vr = fr[y0*64+x0]*c00 + fr[y0*64+x1i]*c01
                       + fr[y1i*64+x0]*c10 + fr[y1i*64+x1i]*c11;
              if (valid){ as += vs; ar += vr; }
            }
          }
          rs_s[cell] = as * 0.25f;
          rr_s[cell] = ar * 0.25f;
        }
        __syncthreads();

        float inv_bw = 1.f/bw, inv_bh = 1.f/bh;
        for (int i = chunk*1024 + t; i < (chunk+1)*1024; i += 160){
          int h = i >> 6, w = i & 63;
          float ry = ((float)h - y1)*inv_bh - 0.5f;
          float rx = ((float)w - x1)*inv_bw - 0.5f;
          bool valid = (ry > -1.f) && (ry < 32.f) && (rx > -1.f) && (rx < 32.f);
          float yc = fminf(fmaxf(ry,0.f),31.f);
          float xc = fminf(fmaxf(rx,0.f),31.f);
          int y0 = (int)floorf(yc), x0 = (int)floorf(xc);
          int y1i = min(y0+1,31), x1i = min(x0+1,31);
          float wy = yc - (float)y0, wx = xc - (float)x0;
          float c00 = (1.f-wy)*(1.f-wx), c01 = (1.f-wy)*wx;
          float c10 = wy*(1.f-wx),       c11 = wy*wx;
          float vs = rs_s[y0*32+x0]*c00 + rs_s[y0*32+x1i]*c01
                   + rs_s[y1i*32+x0]*c10 + rs_s[y1i*32+x1i]*c11;
          float vr = rr_s[y0*32+x0]*c00 + rr_s[y0*32+x1i]*c01
                   + rr_s[y1i*32+x0]*c10 + rr_s[y1i*32+x1i]*c11;
          if (!valid){ vs = 0.f; vr = 0.f; }
          lmax = fmaxf(lmax, vr);
          fwT[(size_t)i*32] = (vs != 0.f) ? vr : -FLT_MAX;
        }
      }
    } else {
      const float* fwp = g_fw0 + b*FHW;
      for (int i = chunk*1024 + t; i < (chunk+1)*1024; i += 160)
        lmax = fmaxf(lmax, fwp[i]);
    }

    lmax = warpReduceMax(lmax);
    if ((t & 31) == 0) smax[t>>5] = lmax;
    __syncthreads();
    if (t < 32){
      float v = (t < 5) ? smax[t] : -FLT_MAX;
      v = warpReduceMax(v);
      if (t == 0){
        int m = (s < NN) ? (1 + s) : 0;
        g_mp4[(b*MM + m)*4 + chunk] = v;
      }
    }

    // -------- last-arrival epilogue (counter scoped to slot blocks) --------
    __threadfence();
    __syncthreads();
    __shared__ int s_old2;
    if (t == 0) s_old2 = atomicAdd(&g_ctr, 1);
    __syncthreads();
    if (s_old2 != K2_TOTAL - 1) return;
    __threadfence();

    __shared__ float mp_s[BB][MM], mg[BB][MM], hh[BB][MM];
    if (t < BB*MM){
      int bb = t/MM, m = t%MM;
      const float* p = g_mp4 + (bb*MM + m)*4;
      mp_s[bb][m] = fmaxf(fmaxf(p[0],p[1]), fmaxf(p[2],p[3]));
    }
    __syncthreads();
    if (t < BB*MM){
      int bb = t/MM, i = t%MM;
      mg[bb][i] = (i == 0) ? mp_s[bb][0] : mp_s[bb][1 + perm[i-1]];
    }
    __syncthreads();
    if (t < BB*MM){
      int bb = t/MM, i = t%MM;
      float a = b1[i];
      #pragma unroll
      for (int j=0;j<MM;j++) a += mg[bb][j]*w1[j*MM+i];
      hh[bb][i] = fmaxf(a, 0.f);
    }
    __syncthreads();
    if (t < BB*MM){
      int bb = t/MM, i = t%MM;
      float a = b2[i];
      #pragma unroll
      for (int j=0;j<MM;j++) a += hh[bb][j]*w2[j*MM+i];
      float sg = 1.f/(1.f + expf(-a));
      if (i == 0) g_scale[bb*MM] = sg; else g_scale[bb*MM + 1 + perm[i-1]] = sg;
    }
    return;
  }

  // ================= roialign path =================
  int r = bid - K2_TOTAL;
  int chalf = r & 1;
  r >>= 1;
  int b  = r / (NN*PH);
  int rem = r % (NN*PH);
  int n  = rem / PH;
  int ph = rem % PH;
  if (masks[b*NN+n] == 0) return;

  int tq = t % 40;
  int cg = t / 40;

  const float* bx = boxes + (b*NN+n)*4;
  float x1 = bx[0]*64.f - 0.5f;
  float y1 = bx[1]*64.f - 0.5f;
  float bw = (bx[2]*64.f - 0.5f - x1) * (1.f/PW);
  float bh = (bx[3]*64.f - 0.5f - y1) * (1.f/PH);

  // --- row (y) coefficients ---
  float Ac0=0.f, Ac1=0.f, Ac2=0.f;
  float yA = y1 + ((float)(2*ph)+0.5f)*0.5f*bh;
  float yB = yA + 0.5f*bh;
  float ycA = fminf(fmaxf(yA,0.f),63.f);
  float ycB = fminf(fmaxf(yB,0.f),63.f);
  int y0A = (int)floorf(ycA), y0B = (int)floorf(ycB);
  int r0 = y0A;
  {
    if (yA > -1.f && yA < 64.f){
      int y1A = min(y0A+1,63);
      float wy = ycA - (float)y0A;
      float w0 = 0.5f*(1.f-wy), w1v = 0.5f*wy;
      int o1 = y1A - r0;
      Ac0 += w0;
      if (o1==0) Ac0 += w1v; else if (o1==1) Ac1 += w1v; else Ac2 += w1v;
    }
    if (yB > -1.f && yB < 64.f){
      int y1B = min(y0B+1,63);
      float wy = ycB - (float)y0B;
      float w0 = 0.5f*(1.f-wy), w1v = 0.5f*wy;
      int o0 = y0B - r0, o1 = y1B - r0;
      if (o0==0) Ac0 += w0; else if (o0==1) Ac1 += w0; else Ac2 += w0;
      if (o1==0) Ac0 += w1v; else if (o1==1) Ac1 += w1v; else Ac2 += w1v;
    }
  }
  bool anyA = (Ac0 != 0.f) || (Ac1 != 0.f) || (Ac2 != 0.f);

  // --- x patch bounds ---
  float xFirst = x1 + 0.25f*bw;
  float xLast  = x1 + 63.5f*0.5f*bw;
  int c_lo = (int)floorf(fminf(fmaxf(xFirst,0.f),63.f));
  int c_hi = min((int)floorf(fminf(fmaxf(xLast ,0.f),63.f)) + 1, 63);
  c_hi = min(c_hi, c_lo + 31);
  int W = c_hi - c_lo + 1;

  // --- stage 1: vertical resample (fp32 math, fp16 vrow store) ---
  if (anyA){
    int rr0 = min(r0  ,63);
    int rr1 = min(r0+1,63);
    int rr2 = min(r0+2,63);
    const float4* base4 = (const float4*)(nhs + (size_t)b*FHW*CC) + chalf*40 + tq;
    const float4* p0 = base4 + (size_t)rr0*64*80;
    const float4* p1 = base4 + (size_t)rr1*64*80;
    const float4* p2 = base4 + (size_t)rr2*64*80;
    #pragma unroll 4
    for (int col=c_lo+cg; col<=c_hi; col+=4){
      float4 a = p0[col*80];
      float4 bb2 = p1[col*80];
      float4 cc2 = p2[col*80];
      float4 v;
      v.x = Ac0*a.x + Ac1*bb2.x + Ac2*cc2.x;
      v.y = Ac0*a.y + Ac1*bb2.y + Ac2*cc2.y;
      v.z = Ac0*a.z + Ac1*bb2.z + Ac2*cc2.z;
      v.w = Ac0*a.w + Ac1*bb2.w + Ac2*cc2.w;
      vrowh[(col-c_lo)*40 + tq] = pack_h4(v);
    }
  } else {
    uint2 z = make_uint2(0u,0u);
    for (int col=cg; col<W; col+=4) vrowh[col*40 + tq] = z;
  }

  // --- per-cell x coefficients + tap offsets ---
  if (t < PW){
    int pw = t;
    float Bc0=0.f, Bc1=0.f, Bc2=0.f;
    float xA = x1 + ((float)(2*pw)+0.5f)*0.5f*bw;
    float xB = xA + 0.5f*bw;
    float xcA = fminf(fmaxf(xA,0.f),63.f);
    float xcB = fminf(fmaxf(xB,0.f),63.f);
    int x0A = (int)floorf(xcA), x0B = (int)floorf(xcB);
    int cb = x0A;
    if (xA > -1.f && xA < 64.f){
      int x1A = min(x0A+1,63);
      float wx = xcA - (float)x0A;
      float w0 = 0.5f*(1.f-wx), w1v = 0.5f*wx;
      int o1 = x1A - cb;
      Bc0 += w0;
      if (o1==0) Bc0 += w1v; else if (o1==1) Bc1 += w1v; else Bc2 += w1v;
    }
    if (xB > -1.f && xB < 64.f){
      int x1B = min(x0B+1,63);
      float wx = xcB - (float)x0B;
      float w0 = 0.5f*(1.f-wx), w1v = 0.5f*wx;
      int o0 = x0B - cb, o1 = x1B - cb;
      if (o0==0) Bc0 += w0; else if (o0==1) Bc1 += w0; else Bc2 += w0;
      if (o1==0) Bc0 += w1v; else if (o1==1) Bc1 += w1v; else Bc2 += w1v;
    }
    int cbr = cb - c_lo;
    s_B[pw][0] = Bc0; s_B[pw][1] = Bc1; s_B[pw][2] = Bc2;
    s_i[pw][0] = min(cbr  , W-1)*40;
    s_i[pw][1] = min(cbr+1, W-1)*40;
    s_i[pw][2] = min(cbr+2, W-1)*40;
  }
  __syncthreads();

  // --- stage 2: 8 consecutive cells per thread, sliding 3-tap window ---
  {
    int base = cg*8;
    uint2* rdst2 = (uint2*)(g_roi_h + (((size_t)(b*NN+n)*PH + ph)*PW)*CC) + chalf*40 + tq;
    int cur0 = s_i[base][0], cur1 = s_i[base][1], cur2 = s_i[base][2];
    float4 v0 = unpack_h4(vrowh[cur0+tq]);
    float4 v1 = unpack_h4(vrowh[cur1+tq]);
    float4 v2 = unpack_h4(vrowh[cur2+tq]);
    #pragma unroll
    for (int k=0;k<8;k++){
      int cell = base + k;
      if (k > 0){
        int n0 = s_i[cell][0];
        if (n0 != cur0){
          if (n0 == cur1){
            v0 = v1; v1 = v2;
            cur0 = cur1; cur1 = cur2;
            cur2 = s_i[cell][2];
            v2 = unpack_h4(vrowh[cur2+tq]);
          } else {
            cur0 = n0; cur1 = s_i[cell][1]; cur2 = s_i[cell][2];
            v0 = unpack_h4(vrowh[cur0+tq]);
            v1 = unpack_h4(vrowh[cur1+tq]);
            v2 = unpack_h4(vrowh[cur2+tq]);
          }
        }
      }
      float B0 = s_B[cell][0], B1 = s_B[cell][1], B2 = s_B[cell][2];
      float4 v;
      v.x = B0*v0.x + B1*v1.x + B2*v2.x;
      v.y = B0*v0.y + B1*v1.y + B2*v2.y;
      v.z = B0*v0.z + B1*v1.z + B2*v2.z;
      v.w = B0*v0.w + B1*v1.w + B2*v2.w;
      rdst2[cell*80] = pack_h4(v);
    }
  }
}

// ---------------------------------------------------------------------------
// Kernel C: 4 pixels per block; coalesced logit prologue on warps 0-3,
// fp16 tap accumulation on all 320 threads.
// ---------------------------------------------------------------------------
__global__ void __launch_bounds__(320) k_final(
    const float* __restrict__ attn,
    const float* __restrict__ boxes,
    float* __restrict__ out)
{
  int pix0 = blockIdx.x*4, b = blockIdx.y;
  int t = threadIdx.x;
  int wid = t >> 5;
  __shared__ float s_w0[4];
  __shared__ float s_coef[4][NN][4];
  __shared__ int   s_base[4][NN][4];
  __shared__ int   s_cnt[4];

  if (wid < 4){
    int pix = pix0 + wid;
    int m = t & 31;
    float fwv = g_fwT[((size_t)b*FHW + pix)*32 + m];
    float sc  = (m < MM) ? g_scale[b*MM + m] : 0.f;
    bool live = (m < MM) && (fwv > -1e37f);
    float logit = live ? fwv*sc : -FLT_MAX;
    float mx = warpReduceMax(logit);
    float e = live ? expf(logit - mx) : 0.f;
    float sum = warpReduceSum(e);
    float w = e / sum;
    if (m == 0) s_w0[wid] = w;

    bool act = (m >= 1) && (m < MM) && (w > 0.f);
    unsigned amask = __ballot_sync(0xffffffffu, act);
    if (act){
      int slot = __popc(amask & ((1u << m) - 1u));
      int n = m - 1;
      const float* bx = boxes + (b*NN+n)*4;
      float x1 = bx[0]*64.f - 0.5f, y1 = bx[1]*64.f - 0.5f;
      float bw = (bx[2]*64.f - 0.5f - x1)*(1.f/PW);
      float bh = (bx[3]*64.f - 0.5f - y1)*(1.f/PH);
      int h = pix >> 6, xw = pix & 63;
      float ry = ((float)h - y1)/bh - 0.5f;
      float rx = ((float)xw - x1)/bw - 0.5f;
      float yc = fminf(fmaxf(ry,0.f),31.f);
      float xc = fminf(fmaxf(rx,0.f),31.f);
      int y0 = (int)floorf(yc), x0 = (int)floorf(xc);
      int y1i = min(y0+1,31), x1i = min(x0+1,31);
      float wy = yc - (float)y0, wx = xc - (float)x0;
      int rb = (b*NN+n)*PH*PW;
      s_coef[wid][slot][0] = w*(1.f-wy)*(1.f-wx); s_base[wid][slot][0] = (rb + y0 *32 + x0 )*(CC/4);
      s_coef[wid][slot][1] = w*(1.f-wy)*wx;       s_base[wid][slot][1] = (rb + y0 *32 + x1i)*(CC/4);
      s_coef[wid][slot][2] = w*wy*(1.f-wx);       s_base[wid][slot][2] = (rb + y1i*32 + x0 )*(CC/4);
      s_coef[wid][slot][3] = w*wy*wx;             s_base[wid][slot][3] = (rb + y1i*32 + x1i)*(CC/4);
    }
    if (m == 0) s_cnt[wid] = __popc(amask);
  }
  __syncthreads();

  int lp = t / 80;          // local pixel 0..3
  int ci = t % 80;          // uint2 (4-channel) index
  int pix = pix0 + lp;
  const float4* a4 = (const float4*)(attn + (size_t)(b*FHW + pix)*CC);
  const uint2* r2 = (const uint2*)g_roi_h;
  float4 av = a4[ci];
  float w0 = s_w0[lp];
  float4 acc = make_float4(w0*av.x, w0*av.y, w0*av.z, w0*av.w);
  int cnt = s_cnt[lp];
  for (int k=0;k<cnt;k++){
    #pragma unroll
    for (int j=0;j<4;j++){
      float cf = s_coef[lp][k][j];
      float4 f = unpack_h4(r2[s_base[lp][k][j] + ci]);
      acc.x += cf*f.x; acc.y += cf*f.y; acc.z += cf*f.z; acc.w += cf*f.w;
    }
  }
  ((float4*)(out + (size_t)(b*FHW + pix)*CC))[ci] = acc;
}

// ---------------------------------------------------------------------------
extern "C" void kernel_launch(void* const* d_in, const int* in_sizes, int n_in,
                              void* d_out, int out_size) {
  const float* nhs      = (const float*)d_in[0];
  const float* attn     = (const float*)d_in[1];
  const float* boxes    = (const float*)d_in[2];
  const int*   masks    = (const int*)  d_in[3];
  const int*   perm     = (const int*)  d_in[4];
  const float* w_reduce = (const float*)d_in[5];
  const float* w1       = (const float*)d_in[6];
  const float* b1       = (const float*)d_in[7];
  const float* w2       = (const float*)d_in[8];
  const float* b2       = (const float*)d_in[9];
  float* out = (float*)d_out;

  k_red<<<RED_BLOCKS, 160>>>(nhs, attn, w_reduce);
  k_main<<<K2_TOTAL + RA_BLOCKS2, 160>>>(nhs, boxes, masks, perm, w1, b1, w2, b2);
  k_final<<<dim3(FHW/4, BB), 320>>>(attn, boxes, out);
}